// round 4
// baseline (speedup 1.0000x reference)
#include <cuda_runtime.h>
#include <cuda_bf16.h>
#include <cstdint>

#define NB   32
#define CC   256
#define HHW  56
#define HW   3136      // 56*56
#define MTOT 100352    // 32*3136
#define K3   2304      // 256*9

// ---------------- device global scratch (no allocations allowed) ----------------
__device__ __align__(256) signed char g_Si[(size_t)MTOT * CC];     // sign activations, NHWC int8 +-1
__device__ __align__(256) signed char g_Bw3i[(size_t)CC * K3];     // binarized 3x3 weights [o][tap*256+c]
__device__ __align__(256) signed char g_Bw1i[(size_t)CC * CC];     // binarized 1x1 weights [o][c]
__device__ float g_scale3[CC];
__device__ float g_scale1[CC];
__device__ __align__(256) float g_conv[(size_t)MTOT * CC];         // conv output, NHWC (reused)
__device__ __align__(256) float g_xmid[(size_t)MTOT * CC];         // stage-1 result, NHWC
__device__ float g_part[CC * 2];                                   // BN sums (zeroed by stats after use)
__device__ float g_bnA[CC];
__device__ float g_bnB[CC];

__device__ __forceinline__ float sgnf(float v) {
    return (v > 0.f) ? 1.f : ((v < 0.f) ? -1.f : 0.f);
}
__device__ __forceinline__ signed char sgn8(float v) {
    return (v > 0.f) ? (signed char)1 : ((v < 0.f) ? (signed char)-1 : (signed char)0);
}

// ---------------- weight prep ----------------
__global__ void wprep3_kernel(const float* __restrict__ w) {
    int o = blockIdx.x, tid = threadIdx.x;
    float s = 0.f;
    for (int k = tid; k < K3; k += 256) {
        float v = w[o * K3 + k];
        int c = k / 9, t = k - c * 9;
        g_Bw3i[(size_t)o * K3 + t * 256 + c] = sgn8(v);
        s += fabsf(v);
    }
    __shared__ float red[256];
    red[tid] = s; __syncthreads();
    for (int st = 128; st > 0; st >>= 1) { if (tid < st) red[tid] += red[tid + st]; __syncthreads(); }
    if (tid == 0) g_scale3[o] = red[0] / (float)K3;
}

__global__ void wprep1_kernel(const float* __restrict__ w) {
    int o = blockIdx.x, tid = threadIdx.x;
    float v = w[o * 256 + tid];
    g_Bw1i[o * 256 + tid] = sgn8(v);
    __shared__ float red[256];
    red[tid] = fabsf(v); __syncthreads();
    for (int st = 128; st > 0; st >>= 1) { if (tid < st) red[tid] += red[tid + st]; __syncthreads(); }
    if (tid == 0) g_scale1[o] = red[0] / 256.f;
}

// ---------------- sign(x + b1_1): NCHW -> NHWC int8 via smem transpose ----------------
__global__ void sign_in_kernel(const float* __restrict__ x, const float* __restrict__ b1) {
    __shared__ float xs[64][65];
    int hw0 = blockIdx.x * 64, c0 = blockIdx.y * 64, n = blockIdx.z;
    int tid = threadIdx.x;
#pragma unroll
    for (int i = 0; i < 16; i++) {
        int e = tid + 256 * i;
        int ci = e >> 6, hwi = e & 63;
        xs[ci][hwi] = x[((size_t)(n * CC + c0 + ci)) * HW + hw0 + hwi];
    }
    __syncthreads();
    int ci = tid & 63;
    float b = b1[c0 + ci];
#pragma unroll
    for (int i = 0; i < 16; i++) {
        int e = tid + 256 * i;
        int hwi = e >> 6;
        g_Si[((size_t)(n * HW + hw0 + hwi)) * CC + c0 + ci] = sgn8(xs[ci][hwi] + b);
    }
}

// ---------------- mma helpers ----------------
__device__ __forceinline__ void ldsm_x4(uint32_t (&r)[4], uint32_t addr) {
    asm volatile("ldmatrix.sync.aligned.m8n8.x4.shared.b16 {%0,%1,%2,%3}, [%4];\n"
                 : "=r"(r[0]), "=r"(r[1]), "=r"(r[2]), "=r"(r[3]) : "r"(addr));
}
__device__ __forceinline__ void imma16832(int (&d)[4], const uint32_t (&a)[4], const uint32_t* b) {
    asm volatile("mma.sync.aligned.m16n8k32.row.col.s32.s8.s8.s32 "
                 "{%0,%1,%2,%3}, {%4,%5,%6,%7}, {%8,%9}, {%0,%1,%2,%3};\n"
                 : "+r"(d[0]), "+r"(d[1]), "+r"(d[2]), "+r"(d[3])
                 : "r"(a[0]), "r"(a[1]), "r"(a[2]), "r"(a[3]), "r"(b[0]), "r"(b[1]));
}
__device__ __forceinline__ void cpasync16(uint32_t dst, const void* src, int sz) {
    asm volatile("{\n\t.reg .u64 g;\n\tcvta.to.global.u64 g, %1;\n\t"
                 "cp.async.cg.shared.global [%0], [g], 16, %2;\n\t}"
                 :: "r"(dst), "l"(src), "r"(sz));
}
// row r (0..127), 16B-segment s (0..15) of a 256B row; XOR swizzle for conflict-free ldsm
__device__ __forceinline__ uint32_t swz(int r, int s) {
    return (uint32_t)(r * 256 + (((s & 8) | ((s ^ r) & 7)) << 4));
}

// ---------------- int8 implicit-GEMM binarized conv, cp.async double-buffered ----------------
// Per CTA: 128 M-rows x 128 outputs. K chunk = one tap = 256 int8.
// A = g_Si (NHWC int8 +-1), B = binarized int8 weights, acc in s32 regs.
#define STAGE_BYTES 65536   // A 32K + B 32K
#define DSMEM_BYTES (2 * STAGE_BYTES)

template <int TAPS>
__global__ void __launch_bounds__(256) conv_i8_kernel() {
    extern __shared__ __align__(16) char dsm[];
    __shared__ float s_scale[128];
    __shared__ float s_ps[32][2];

    const int tid = threadIdx.x;
    const int lane = tid & 31;
    const int warp = tid >> 5;
    const int wm = warp >> 2, wn = warp & 3;      // 2 warps along M, 4 along N
    const int m0 = blockIdx.x * 128, o0 = blockIdx.y * 128;

    const signed char* __restrict__ Bw = (TAPS == 9) ? g_Bw3i : g_Bw1i;
    const float* __restrict__ scl = (TAPS == 9) ? g_scale3 : g_scale1;
    const int ldB = TAPS * 256;

    if (tid < 128) s_scale[tid] = scl[o0 + tid];

    const uint32_t sbase = (uint32_t)__cvta_generic_to_shared(dsm);

    int acc[4][4][4];
#pragma unroll
    for (int a = 0; a < 4; a++)
#pragma unroll
        for (int b = 0; b < 4; b++)
#pragma unroll
            for (int c = 0; c < 4; c++) acc[a][b][c] = 0;

    // load thread mapping: 2 threads per row, 8 segments each
    const int r = tid >> 1;
    const int sb = (tid & 1) * 8;

    auto load_chunk = [&](int t, int stg) {
        uint32_t stA = sbase + stg * STAGE_BYTES;
        uint32_t stB = stA + 32768;
        int dy = (TAPS == 9) ? (t / 3 - 1) : 0;
        int dx = (TAPS == 9) ? (t % 3 - 1) : 0;
        int m = m0 + r;
        int n = m / HW; int hw = m - n * HW;
        int h = hw / HHW; int w = hw - h * HHW;
        int hh = h + dy, ww = w + dx;
        bool valid = ((unsigned)hh < (unsigned)HHW) && ((unsigned)ww < (unsigned)HHW);
        const signed char* srcA = valid ? (g_Si + ((size_t)(n * HW + hh * HHW + ww)) * 256) : g_Si;
        int sz = valid ? 16 : 0;
        const signed char* srcB = Bw + (size_t)(o0 + r) * ldB + t * 256;
#pragma unroll
        for (int j = 0; j < 8; j++) {
            int s = sb + j;
            cpasync16(stA + swz(r, s), srcA + s * 16, sz);
            cpasync16(stB + swz(r, s), srcB + s * 16, 16);
        }
        asm volatile("cp.async.commit_group;" ::: "memory");
    };

    load_chunk(0, 0);

#pragma unroll 1
    for (int ck = 0; ck < TAPS; ck++) {
        int stg = ck & 1;
        if (ck + 1 < TAPS) {
            load_chunk(ck + 1, stg ^ 1);
            asm volatile("cp.async.wait_group 1;" ::: "memory");
        } else {
            asm volatile("cp.async.wait_group 0;" ::: "memory");
        }
        __syncthreads();

        uint32_t stA = sbase + stg * STAGE_BYTES;
        uint32_t stB = stA + 32768;
#pragma unroll
        for (int ks = 0; ks < 8; ks++) {
            uint32_t a[4][4];
#pragma unroll
            for (int mf = 0; mf < 4; mf++) {
                int row = wm * 64 + mf * 16 + (lane & 15);
                int seg = 2 * ks + ((lane >> 4) & 1);
                ldsm_x4(a[mf], stA + swz(row, seg));
            }
            uint32_t bq[2][4];
#pragma unroll
            for (int g = 0; g < 2; g++) {
                int row = wn * 32 + g * 16 + (lane & 7) + (((lane >> 4) & 1) << 3);
                int seg = 2 * ks + ((lane >> 3) & 1);
                ldsm_x4(bq[g], stB + swz(row, seg));
            }
#pragma unroll
            for (int mf = 0; mf < 4; mf++)
#pragma unroll
                for (int nf = 0; nf < 4; nf++)
                    imma16832(acc[mf][nf], a[mf], &bq[nf >> 1][(nf & 1) * 2]);
        }
        __syncthreads();
    }

    // epilogue: regs -> smem transpose (scaled) -> coalesced NHWC stores + BN partial sums
    float* Cs = (float*)dsm;
#pragma unroll 1
    for (int j = 0; j < 4; j++) {
        if (tid < 64) s_ps[tid >> 1][tid & 1] = 0.f;
        if (wn == j) {
#pragma unroll
            for (int mf = 0; mf < 4; mf++)
#pragma unroll
                for (int nf = 0; nf < 4; nf++) {
                    int row = wm * 64 + mf * 16 + (lane >> 2);
                    int col = nf * 8 + (lane & 3) * 2;
                    Cs[row * 33 + col]           = (float)acc[mf][nf][0];
                    Cs[row * 33 + col + 1]       = (float)acc[mf][nf][1];
                    Cs[(row + 8) * 33 + col]     = (float)acc[mf][nf][2];
                    Cs[(row + 8) * 33 + col + 1] = (float)acc[mf][nf][3];
                }
        }
        __syncthreads();
        {
            int c = tid & 31;
            float sc = s_scale[j * 32 + c];
            float s1 = 0.f, s2 = 0.f;
            int o = o0 + j * 32 + c;
#pragma unroll
            for (int i = 0; i < 16; i++) {
                int e = tid + 256 * i;
                int row = e >> 5;
                float v = Cs[row * 33 + c] * sc;
                g_conv[(size_t)(m0 + row) * 256 + o] = v;
                s1 += v; s2 += v * v;
            }
            atomicAdd(&s_ps[c][0], s1);
            atomicAdd(&s_ps[c][1], s2);
        }
        __syncthreads();
        if (tid < 64) {
            atomicAdd(&g_part[(o0 + j * 32 + (tid >> 1)) * 2 + (tid & 1)], s_ps[tid >> 1][tid & 1]);
        }
        __syncthreads();
    }
}

// ---------------- BN stats: fold to scale/shift, then zero accumulators for next use ----------------
__global__ void stats_kernel(const float* __restrict__ gamma, const float* __restrict__ beta) {
    int c = threadIdx.x;
    float s1 = g_part[c * 2];
    float s2 = g_part[c * 2 + 1];
    float mean = s1 / (float)MTOT;
    float var  = s2 / (float)MTOT - mean * mean;
    float inv  = rsqrtf(var + 1e-5f);
    g_bnA[c] = gamma[c] * inv;
    g_bnB[c] = beta[c] - mean * gamma[c] * inv;
    g_part[c * 2] = 0.f;
    g_part[c * 2 + 1] = 0.f;
}

// ---------------- stage-1 tail: BN + residual + bias + PReLU + bias; emit x_mid & sign ----------------
__global__ void fuse1_kernel(const float* __restrict__ x, const float* __restrict__ b12,
                             const float* __restrict__ a1, const float* __restrict__ b13,
                             const float* __restrict__ b21) {
    __shared__ float xs[64][65];
    int hw0 = blockIdx.x * 64, c0 = blockIdx.y * 64, n = blockIdx.z;
    int tid = threadIdx.x;
#pragma unroll
    for (int i = 0; i < 16; i++) {
        int e = tid + 256 * i;
        int ci = e >> 6, hwi = e & 63;
        xs[ci][hwi] = x[((size_t)(n * CC + c0 + ci)) * HW + hw0 + hwi];
    }
    __syncthreads();
    int ci = tid & 63, c = c0 + ci;
    float A = g_bnA[c], B = g_bnB[c];
    float vb12 = b12[c], va = a1[c], vb13 = b13[c], vb21 = b21[c];
#pragma unroll
    for (int i = 0; i < 16; i++) {
        int e = tid + 256 * i;
        int hwi = e >> 6;
        size_t idx = ((size_t)(n * HW + hw0 + hwi)) * CC + c;
        float y = xs[ci][hwi] + g_conv[idx] * A + B;
        y += vb12;
        y = (y >= 0.f) ? y : va * y;
        y += vb13;
        g_xmid[idx] = y;
        g_Si[idx] = sgn8(y + vb21);
    }
}

// ---------------- stage-2 tail: BN + residual + bias + PReLU + bias; NHWC -> NCHW out ----------------
__global__ void fuse2_kernel(const float* __restrict__ b22, const float* __restrict__ a2,
                             const float* __restrict__ b23, float* __restrict__ out) {
    __shared__ float ys[64][65];
    int hw0 = blockIdx.x * 64, c0 = blockIdx.y * 64, n = blockIdx.z;
    int tid = threadIdx.x;
    int ci = tid & 63, c = c0 + ci;
    float A = g_bnA[c], B = g_bnB[c];
    float vb22 = b22[c], va = a2[c], vb23 = b23[c];
#pragma unroll
    for (int i = 0; i < 16; i++) {
        int e = tid + 256 * i;
        int hwi = e >> 6;
        size_t idx = ((size_t)(n * HW + hw0 + hwi)) * CC + c;
        float y = g_conv[idx] * A + B + g_xmid[idx];
        y += vb22;
        y = (y >= 0.f) ? y : va * y;
        y += vb23;
        ys[ci][hwi] = y;
    }
    __syncthreads();
#pragma unroll
    for (int i = 0; i < 16; i++) {
        int e = tid + 256 * i;
        int c2 = e >> 6, hwi = e & 63;
        out[((size_t)(n * CC + c0 + c2)) * HW + hw0 + hwi] = ys[c2][hwi];
    }
}

// ---------------- launch ----------------
extern "C" void kernel_launch(void* const* d_in, const int* in_sizes, int n_in,
                              void* d_out, int out_size) {
    (void)in_sizes; (void)n_in; (void)out_size;
    const float* x     = (const float*)d_in[0];
    const float* b1_1  = (const float*)d_in[1];
    const float* w3x3  = (const float*)d_in[2];
    const float* bn1_g = (const float*)d_in[3];
    const float* bn1_b = (const float*)d_in[4];
    const float* b1_2  = (const float*)d_in[5];
    const float* a1    = (const float*)d_in[6];
    const float* b1_3  = (const float*)d_in[7];
    const float* b2_1  = (const float*)d_in[8];
    const float* wres  = (const float*)d_in[9];
    const float* bn2_g = (const float*)d_in[10];
    const float* bn2_b = (const float*)d_in[11];
    const float* b2_2  = (const float*)d_in[12];
    const float* a2    = (const float*)d_in[13];
    const float* b2_3  = (const float*)d_in[14];
    float* out = (float*)d_out;

    static int attr_done = 0;
    if (!attr_done) {
        cudaFuncSetAttribute(conv_i8_kernel<9>, cudaFuncAttributeMaxDynamicSharedMemorySize, DSMEM_BYTES);
        cudaFuncSetAttribute(conv_i8_kernel<1>, cudaFuncAttributeMaxDynamicSharedMemorySize, DSMEM_BYTES);
        attr_done = 1;
    }

    dim3 tileGrid(49, 4, 32);
    dim3 convGrid(784, 2);

    wprep3_kernel<<<256, 256>>>(w3x3);
    wprep1_kernel<<<256, 256>>>(wres);
    sign_in_kernel<<<tileGrid, 256>>>(x, b1_1);
    conv_i8_kernel<9><<<convGrid, 256, DSMEM_BYTES>>>();
    stats_kernel<<<1, 256>>>(bn1_g, bn1_b);
    fuse1_kernel<<<tileGrid, 256>>>(x, b1_2, a1, b1_3, b2_1);
    conv_i8_kernel<1><<<convGrid, 256, DSMEM_BYTES>>>();
    stats_kernel<<<1, 256>>>(bn2_g, bn2_b);
    fuse2_kernel<<<tileGrid, 256>>>(b2_2, a2, b2_3, out);
}

// round 5
// speedup vs baseline: 1.1471x; 1.1471x over previous
#include <cuda_runtime.h>
#include <cuda_bf16.h>
#include <cstdint>

#define NB   32
#define CC   256
#define HHW  56
#define HW   3136      // 56*56
#define MTOT 100352    // 32*3136
#define K3   2304      // 256*9

// ---------------- device global scratch (no allocations allowed) ----------------
__device__ __align__(256) __nv_bfloat16 g_S[(size_t)MTOT * CC];    // sign activations, NHWC bf16 +-1
__device__ __align__(256) __nv_bfloat16 g_Bw3[(size_t)CC * K3];    // binarized 3x3 weights [o][tap*256+c]
__device__ __align__(256) __nv_bfloat16 g_Bw1[(size_t)CC * CC];    // binarized 1x1 weights [o][c]
__device__ float g_scale3[CC];
__device__ float g_scale1[CC];
__device__ __align__(256) float g_conv[(size_t)MTOT * CC];         // conv output, NHWC (reused)
__device__ __align__(256) float g_xmid[(size_t)MTOT * CC];         // stage-1 result, NHWC
__device__ float g_part[CC * 2];                                   // BN sums (zeroed by stats after use)
__device__ float g_bnA[CC];
__device__ float g_bnB[CC];

__device__ __forceinline__ float sgnf(float v) {
    return (v > 0.f) ? 1.f : ((v < 0.f) ? -1.f : 0.f);
}

// ---------------- weight prep ----------------
__global__ void wprep3_kernel(const float* __restrict__ w) {
    int o = blockIdx.x, tid = threadIdx.x;
    float s = 0.f;
    for (int k = tid; k < K3; k += 256) {
        float v = w[o * K3 + k];
        int c = k / 9, t = k - c * 9;
        g_Bw3[(size_t)o * K3 + t * 256 + c] = __float2bfloat16(sgnf(v));
        s += fabsf(v);
    }
    __shared__ float red[256];
    red[tid] = s; __syncthreads();
    for (int st = 128; st > 0; st >>= 1) { if (tid < st) red[tid] += red[tid + st]; __syncthreads(); }
    if (tid == 0) g_scale3[o] = red[0] / (float)K3;
}

__global__ void wprep1_kernel(const float* __restrict__ w) {
    int o = blockIdx.x, tid = threadIdx.x;
    float v = w[o * 256 + tid];
    g_Bw1[o * 256 + tid] = __float2bfloat16(sgnf(v));
    __shared__ float red[256];
    red[tid] = fabsf(v); __syncthreads();
    for (int st = 128; st > 0; st >>= 1) { if (tid < st) red[tid] += red[tid + st]; __syncthreads(); }
    if (tid == 0) g_scale1[o] = red[0] / 256.f;
}

// ---------------- sign(x + b1_1): NCHW -> NHWC bf16 via smem transpose ----------------
__global__ void sign_in_kernel(const float* __restrict__ x, const float* __restrict__ b1) {
    __shared__ float xs[64][65];
    int hw0 = blockIdx.x * 64, c0 = blockIdx.y * 64, n = blockIdx.z;
    int tid = threadIdx.x;
#pragma unroll
    for (int i = 0; i < 16; i++) {
        int e = tid + 256 * i;
        int ci = e >> 6, hwi = e & 63;
        xs[ci][hwi] = x[((size_t)(n * CC + c0 + ci)) * HW + hw0 + hwi];
    }
    __syncthreads();
    int ci = tid & 63;
    float b = b1[c0 + ci];
#pragma unroll
    for (int i = 0; i < 16; i++) {
        int e = tid + 256 * i;
        int hwi = e >> 6;
        g_S[((size_t)(n * HW + hw0 + hwi)) * CC + c0 + ci] = __float2bfloat16(sgnf(xs[ci][hwi] + b));
    }
}

// ---------------- mma helpers ----------------
__device__ __forceinline__ void ldsm_x4(uint32_t (&r)[4], uint32_t addr) {
    asm volatile("ldmatrix.sync.aligned.m8n8.x4.shared.b16 {%0,%1,%2,%3}, [%4];\n"
                 : "=r"(r[0]), "=r"(r[1]), "=r"(r[2]), "=r"(r[3]) : "r"(addr));
}
__device__ __forceinline__ void mma16816(float (&d)[4], const uint32_t (&a)[4], const uint32_t* b) {
    asm volatile("mma.sync.aligned.m16n8k16.row.col.f32.bf16.bf16.f32 "
                 "{%0,%1,%2,%3}, {%4,%5,%6,%7}, {%8,%9}, {%0,%1,%2,%3};\n"
                 : "+f"(d[0]), "+f"(d[1]), "+f"(d[2]), "+f"(d[3])
                 : "r"(a[0]), "r"(a[1]), "r"(a[2]), "r"(a[3]), "r"(b[0]), "r"(b[1]));
}
__device__ __forceinline__ void cpasync16(uint32_t dst, const void* src, int sz) {
    asm volatile("{\n\t.reg .u64 g;\n\tcvta.to.global.u64 g, %1;\n\t"
                 "cp.async.cg.shared.global [%0], [g], 16, %2;\n\t}"
                 :: "r"(dst), "l"(src), "r"(sz));
}
// 128B rows, 8 x 16B segments; XOR swizzle -> conflict-free ldmatrix + cp.async
__device__ __forceinline__ uint32_t swz(int r, int s) {
    return (uint32_t)(r * 128 + ((s ^ (r & 7)) << 4));
}

// ---------------- bf16 implicit-GEMM binarized conv, 4-stage cp.async ring ----------------
// Per CTA: 128 M-rows x 128 outputs. K chunk = 64 channels (128B/row).
// A = g_S (NHWC bf16 +-1), B = binarized bf16 weights, fp32 accum in regs.
#define STAGE_BYTES 32768   // A 16K + B 16K
#define DSMEM_BYTES (4 * STAGE_BYTES)

template <int TAPS>
__global__ void __launch_bounds__(256) conv_bf_kernel() {
    extern __shared__ __align__(16) char dsm[];
    __shared__ float s_scale[128];
    __shared__ float s_ps[32][2];

    const int tid = threadIdx.x;
    const int lane = tid & 31;
    const int warp = tid >> 5;
    const int wm = warp >> 2, wn = warp & 3;      // 2 warps along M, 4 along N
    const int m0 = blockIdx.x * 128, o0 = blockIdx.y * 128;
    constexpr int NC = TAPS * 4;

    const __nv_bfloat16* __restrict__ Bw = (TAPS == 9) ? g_Bw3 : g_Bw1;
    const float* __restrict__ scl = (TAPS == 9) ? g_scale3 : g_scale1;
    const int ldB = TAPS * 256;

    if (tid < 128) s_scale[tid] = scl[o0 + tid];

    const uint32_t sbase = (uint32_t)__cvta_generic_to_shared(dsm);

    float acc[4][4][4];
#pragma unroll
    for (int a = 0; a < 4; a++)
#pragma unroll
        for (int b = 0; b < 4; b++)
#pragma unroll
            for (int c = 0; c < 4; c++) acc[a][b][c] = 0.f;

    // loader mapping: 2 threads per row, 4 x 16B segments each
    const int lr = tid >> 1;
    const int sb = (tid & 1) * 4;

    auto load_chunk = [&](int ck, int stg) {
        int t = ck >> 2;
        int kc = (ck & 3) * 64;          // bf16 element offset within tap
        uint32_t stA = sbase + stg * STAGE_BYTES;
        uint32_t stB = stA + 16384;
        int dy = (TAPS == 9) ? (t / 3 - 1) : 0;
        int dx = (TAPS == 9) ? (t % 3 - 1) : 0;
        int m = m0 + lr;
        int n = m / HW; int hw = m - n * HW;
        int h = hw / HHW; int w = hw - h * HHW;
        int hh = h + dy, ww = w + dx;
        bool valid = ((unsigned)hh < (unsigned)HHW) && ((unsigned)ww < (unsigned)HHW);
        const __nv_bfloat16* srcA = valid
            ? (g_S + ((size_t)(n * HW + hh * HHW + ww)) * 256 + kc) : g_S;
        int sz = valid ? 16 : 0;
        const __nv_bfloat16* srcB = Bw + (size_t)(o0 + lr) * ldB + t * 256 + kc;
#pragma unroll
        for (int j = 0; j < 4; j++) {
            int s = sb + j;
            cpasync16(stA + swz(lr, s), srcA + s * 8, sz);
            cpasync16(stB + swz(lr, s), srcB + s * 8, 16);
        }
        asm volatile("cp.async.commit_group;" ::: "memory");
    };

    // prologue: 3 chunks in flight
    load_chunk(0, 0);
    load_chunk(1, 1);
    load_chunk(2, 2);

#pragma unroll 1
    for (int ck = 0; ck < NC; ck++) {
        // wait until chunk ck's group is complete
        if (ck <= NC - 3)      asm volatile("cp.async.wait_group 2;" ::: "memory");
        else if (ck == NC - 2) asm volatile("cp.async.wait_group 1;" ::: "memory");
        else                   asm volatile("cp.async.wait_group 0;" ::: "memory");
        __syncthreads();

        if (ck + 3 < NC) load_chunk(ck + 3, (ck + 3) & 3);

        uint32_t stA = sbase + (ck & 3) * STAGE_BYTES;
        uint32_t stB = stA + 16384;
#pragma unroll
        for (int ks = 0; ks < 4; ks++) {
            int kk = ks * 16;
            uint32_t a[4][4];
#pragma unroll
            for (int mf = 0; mf < 4; mf++) {
                int row = wm * 64 + mf * 16 + (lane & 15);
                int seg = (kk >> 3) + (lane >> 4);
                ldsm_x4(a[mf], stA + swz(row, seg));
            }
            uint32_t bq[2][4];
#pragma unroll
            for (int g = 0; g < 2; g++) {
                int row = wn * 32 + g * 16 + (lane & 7) + (((lane >> 4) & 1) << 3);
                int seg = (kk >> 3) + ((lane >> 3) & 1);
                ldsm_x4(bq[g], stB + swz(row, seg));
            }
#pragma unroll
            for (int mf = 0; mf < 4; mf++)
#pragma unroll
                for (int nf = 0; nf < 4; nf++)
                    mma16816(acc[mf][nf], a[mf], &bq[nf >> 1][(nf & 1) * 2]);
        }
        // no trailing barrier: next iteration's leading barrier orders stage reuse
        // (loads for ck+4 are issued only after all warps finished compute ck)
    }
    __syncthreads();

    // epilogue: regs -> smem transpose (scaled) -> coalesced NHWC stores + fused BN sums
    float* Cs = (float*)dsm;
#pragma unroll 1
    for (int j = 0; j < 4; j++) {
        if (tid < 64) s_ps[tid >> 1][tid & 1] = 0.f;
        if (wn == j) {
#pragma unroll
            for (int mf = 0; mf < 4; mf++)
#pragma unroll
                for (int nf = 0; nf < 4; nf++) {
                    int row = wm * 64 + mf * 16 + (lane >> 2);
                    int col = nf * 8 + (lane & 3) * 2;
                    Cs[row * 33 + col]           = acc[mf][nf][0];
                    Cs[row * 33 + col + 1]       = acc[mf][nf][1];
                    Cs[(row + 8) * 33 + col]     = acc[mf][nf][2];
                    Cs[(row + 8) * 33 + col + 1] = acc[mf][nf][3];
                }
        }
        __syncthreads();
        {
            int c = tid & 31;
            float sc = s_scale[j * 32 + c];
            float s1 = 0.f, s2 = 0.f;
            int o = o0 + j * 32 + c;
#pragma unroll
            for (int i = 0; i < 16; i++) {
                int e = tid + 256 * i;
                int row = e >> 5;
                float v = Cs[row * 33 + c] * sc;
                g_conv[(size_t)(m0 + row) * 256 + o] = v;
                s1 += v; s2 += v * v;
            }
            atomicAdd(&s_ps[c][0], s1);
            atomicAdd(&s_ps[c][1], s2);
        }
        __syncthreads();
        if (tid < 64) {
            atomicAdd(&g_part[(o0 + j * 32 + (tid >> 1)) * 2 + (tid & 1)], s_ps[tid >> 1][tid & 1]);
        }
        __syncthreads();
    }
}

// ---------------- BN stats: fold to scale/shift, then zero accumulators for next use ----------------
__global__ void stats_kernel(const float* __restrict__ gamma, const float* __restrict__ beta) {
    int c = threadIdx.x;
    float s1 = g_part[c * 2];
    float s2 = g_part[c * 2 + 1];
    float mean = s1 / (float)MTOT;
    float var  = s2 / (float)MTOT - mean * mean;
    float inv  = rsqrtf(var + 1e-5f);
    g_bnA[c] = gamma[c] * inv;
    g_bnB[c] = beta[c] - mean * gamma[c] * inv;
    g_part[c * 2] = 0.f;
    g_part[c * 2 + 1] = 0.f;
}

// ---------------- stage-1 tail: BN + residual + bias + PReLU + bias; emit x_mid & sign ----------------
__global__ void fuse1_kernel(const float* __restrict__ x, const float* __restrict__ b12,
                             const float* __restrict__ a1, const float* __restrict__ b13,
                             const float* __restrict__ b21) {
    __shared__ float xs[64][65];
    int hw0 = blockIdx.x * 64, c0 = blockIdx.y * 64, n = blockIdx.z;
    int tid = threadIdx.x;
#pragma unroll
    for (int i = 0; i < 16; i++) {
        int e = tid + 256 * i;
        int ci = e >> 6, hwi = e & 63;
        xs[ci][hwi] = x[((size_t)(n * CC + c0 + ci)) * HW + hw0 + hwi];
    }
    __syncthreads();
    int ci = tid & 63, c = c0 + ci;
    float A = g_bnA[c], B = g_bnB[c];
    float vb12 = b12[c], va = a1[c], vb13 = b13[c], vb21 = b21[c];
#pragma unroll
    for (int i = 0; i < 16; i++) {
        int e = tid + 256 * i;
        int hwi = e >> 6;
        size_t idx = ((size_t)(n * HW + hw0 + hwi)) * CC + c;
        float y = xs[ci][hwi] + g_conv[idx] * A + B;
        y += vb12;
        y = (y >= 0.f) ? y : va * y;
        y += vb13;
        g_xmid[idx] = y;
        g_S[idx] = __float2bfloat16(sgnf(y + vb21));
    }
}

// ---------------- stage-2 tail: BN + residual + bias + PReLU + bias; NHWC -> NCHW out ----------------
__global__ void fuse2_kernel(const float* __restrict__ b22, const float* __restrict__ a2,
                             const float* __restrict__ b23, float* __restrict__ out) {
    __shared__ float ys[64][65];
    int hw0 = blockIdx.x * 64, c0 = blockIdx.y * 64, n = blockIdx.z;
    int tid = threadIdx.x;
    int ci = tid & 63, c = c0 + ci;
    float A = g_bnA[c], B = g_bnB[c];
    float vb22 = b22[c], va = a2[c], vb23 = b23[c];
#pragma unroll
    for (int i = 0; i < 16; i++) {
        int e = tid + 256 * i;
        int hwi = e >> 6;
        size_t idx = ((size_t)(n * HW + hw0 + hwi)) * CC + c;
        float y = g_conv[idx] * A + B + g_xmid[idx];
        y += vb22;
        y = (y >= 0.f) ? y : va * y;
        y += vb23;
        ys[ci][hwi] = y;
    }
    __syncthreads();
#pragma unroll
    for (int i = 0; i < 16; i++) {
        int e = tid + 256 * i;
        int c2 = e >> 6, hwi = e & 63;
        out[((size_t)(n * CC + c0 + c2)) * HW + hw0 + hwi] = ys[c2][hwi];
    }
}

// ---------------- launch ----------------
extern "C" void kernel_launch(void* const* d_in, const int* in_sizes, int n_in,
                              void* d_out, int out_size) {
    (void)in_sizes; (void)n_in; (void)out_size;
    const float* x     = (const float*)d_in[0];
    const float* b1_1  = (const float*)d_in[1];
    const float* w3x3  = (const float*)d_in[2];
    const float* bn1_g = (const float*)d_in[3];
    const float* bn1_b = (const float*)d_in[4];
    const float* b1_2  = (const float*)d_in[5];
    const float* a1    = (const float*)d_in[6];
    const float* b1_3  = (const float*)d_in[7];
    const float* b2_1  = (const float*)d_in[8];
    const float* wres  = (const float*)d_in[9];
    const float* bn2_g = (const float*)d_in[10];
    const float* bn2_b = (const float*)d_in[11];
    const float* b2_2  = (const float*)d_in[12];
    const float* a2    = (const float*)d_in[13];
    const float* b2_3  = (const float*)d_in[14];
    float* out = (float*)d_out;

    cudaFuncSetAttribute(conv_bf_kernel<9>, cudaFuncAttributeMaxDynamicSharedMemorySize, DSMEM_BYTES);
    cudaFuncSetAttribute(conv_bf_kernel<1>, cudaFuncAttributeMaxDynamicSharedMemorySize, DSMEM_BYTES);

    dim3 tileGrid(49, 4, 32);
    dim3 convGrid(784, 2);

    wprep3_kernel<<<256, 256>>>(w3x3);
    wprep1_kernel<<<256, 256>>>(wres);
    sign_in_kernel<<<tileGrid, 256>>>(x, b1_1);
    conv_bf_kernel<9><<<convGrid, 256, DSMEM_BYTES>>>();
    stats_kernel<<<1, 256>>>(bn1_g, bn1_b);
    fuse1_kernel<<<tileGrid, 256>>>(x, b1_2, a1, b1_3, b2_1);
    conv_bf_kernel<1><<<convGrid, 256, DSMEM_BYTES>>>();
    stats_kernel<<<1, 256>>>(bn2_g, bn2_b);
    fuse2_kernel<<<tileGrid, 256>>>(b2_2, a2, b2_3, out);
}

// round 8
// speedup vs baseline: 2.0478x; 1.7852x over previous
#include <cuda_runtime.h>
#include <cuda_bf16.h>
#include <cstdint>

#define NB    32
#define CC    256
#define HHW   56
#define WPAD  58
#define HWP   3364          // 58*58
#define MP    107648        // 32*3364 = 841*128
#define GURD  64
#define ROWS_SP (GURD + MP + 128)
#define HW    3136
#define MTOT  100352
#define K3    2304

// ---------------- device global scratch (zero-initialized; pads never written -> stay 0) ----------------
__device__ __align__(256) __nv_bfloat16 g_Sp[(size_t)ROWS_SP * CC];   // padded NHWC sign acts (bf16 +-1, pads 0)
__device__ __align__(256) __nv_bfloat16 g_Bp3[(size_t)36 * 256 * 64]; // w3x3: [tap*4+kc][o][swizzled 64ch]
__device__ __align__(256) __nv_bfloat16 g_Bp1[(size_t)4 * 256 * 64];  // wres:  [kc][o][swizzled 64ch]
__device__ float g_scale3[CC];
__device__ float g_scale1[CC];
__device__ __align__(256) float g_conv[(size_t)MP * CC];              // padded NHWC conv out
__device__ __align__(256) float g_xmid[(size_t)MP * CC];              // padded NHWC stage-1 result
__device__ float g_part[CC * 2];                                      // BN sums (zeroed by stats after use)
__device__ float g_bnA[CC];
__device__ float g_bnB[CC];

__device__ __forceinline__ float sgnf(float v) {
    return (v > 0.f) ? 1.f : ((v < 0.f) ? -1.f : 0.f);
}

// ---------------- weight prep: binarize + rearrange into bulk-copy-ready swizzled blocks ----------------
__global__ void wprep3_kernel(const float* __restrict__ w) {
    int o = blockIdx.x, tid = threadIdx.x;
    float s = 0.f;
    for (int k = tid; k < K3; k += 256) {
        float v = w[o * K3 + k];
        int c = k / 9, t = k - c * 9;
        int kc = c >> 6, c64 = c & 63;
        int pos = (c64 >> 3) ^ (o & 7);
        g_Bp3[((size_t)((t * 4 + kc) * 256 + o)) * 64 + pos * 8 + (c64 & 7)] = __float2bfloat16(sgnf(v));
        s += fabsf(v);
    }
    __shared__ float red[256];
    red[tid] = s; __syncthreads();
    for (int st = 128; st > 0; st >>= 1) { if (tid < st) red[tid] += red[tid + st]; __syncthreads(); }
    if (tid == 0) g_scale3[o] = red[0] / (float)K3;
}

__global__ void wprep1_kernel(const float* __restrict__ w) {
    int o = blockIdx.x, tid = threadIdx.x;
    float v = w[o * 256 + tid];
    int kc = tid >> 6, c64 = tid & 63;
    int pos = (c64 >> 3) ^ (o & 7);
    g_Bp1[((size_t)(kc * 256 + o)) * 64 + pos * 8 + (c64 & 7)] = __float2bfloat16(sgnf(v));
    __shared__ float red[256];
    red[tid] = fabsf(v); __syncthreads();
    for (int st = 128; st > 0; st >>= 1) { if (tid < st) red[tid] += red[tid + st]; __syncthreads(); }
    if (tid == 0) g_scale1[o] = red[0] / 256.f;
}

// ---------------- sign(x + b1_1): NCHW -> padded NHWC bf16 ----------------
__global__ void sign_in_kernel(const float* __restrict__ x, const float* __restrict__ b1) {
    __shared__ float xs[64][65];
    int hw0 = blockIdx.x * 64, c0 = blockIdx.y * 64, n = blockIdx.z;
    int tid = threadIdx.x;
#pragma unroll
    for (int i = 0; i < 16; i++) {
        int e = tid + 256 * i;
        int ci = e >> 6, hwi = e & 63;
        xs[ci][hwi] = x[((size_t)(n * CC + c0 + ci)) * HW + hw0 + hwi];
    }
    __syncthreads();
    int ci = tid & 63, c = c0 + ci;
    float b = b1[c];
#pragma unroll
    for (int i = 0; i < 16; i++) {
        int e = tid + 256 * i;
        int hwi = e >> 6;
        int hw = hw0 + hwi;
        int h = hw / HHW, w = hw - h * HHW;
        size_t prow = (size_t)n * HWP + (h + 1) * WPAD + (w + 1);
        g_Sp[(GURD + prow) * CC + c] = __float2bfloat16(sgnf(xs[ci][hwi] + b));
    }
}

// ---------------- mma helpers ----------------
__device__ __forceinline__ void ldsm_x4(uint32_t (&r)[4], uint32_t addr) {
    asm volatile("ldmatrix.sync.aligned.m8n8.x4.shared.b16 {%0,%1,%2,%3}, [%4];\n"
                 : "=r"(r[0]), "=r"(r[1]), "=r"(r[2]), "=r"(r[3]) : "r"(addr));
}
__device__ __forceinline__ void mma16816(float (&d)[4], const uint32_t (&a)[4], const uint32_t* b) {
    asm volatile("mma.sync.aligned.m16n8k16.row.col.f32.bf16.bf16.f32 "
                 "{%0,%1,%2,%3}, {%4,%5,%6,%7}, {%8,%9}, {%0,%1,%2,%3};\n"
                 : "+f"(d[0]), "+f"(d[1]), "+f"(d[2]), "+f"(d[3])
                 : "r"(a[0]), "r"(a[1]), "r"(a[2]), "r"(a[3]), "r"(b[0]), "r"(b[1]));
}
__device__ __forceinline__ void cpasync16(uint32_t dst, const void* src) {
    asm volatile("{\n\t.reg .u64 g;\n\tcvta.to.global.u64 g, %1;\n\t"
                 "cp.async.cg.shared.global [%0], [g], 16;\n\t}"
                 :: "r"(dst), "l"(src));
}
__device__ __forceinline__ uint32_t swz(int r, int s) {   // 128B rows, 8 x 16B segs
    return (uint32_t)(r * 128 + ((s ^ (r & 7)) << 4));
}
__device__ __forceinline__ void mbar_wait(uint32_t mbar, uint32_t parity) {
    asm volatile("{\n\t.reg .pred P1;\n\t"
                 "WAIT_%=:\n\t"
                 "mbarrier.try_wait.parity.acquire.cta.shared::cta.b64 P1, [%0], %1, 0x989680;\n\t"
                 "@P1 bra.uni DONE_%=;\n\t"
                 "bra.uni WAIT_%=;\n\t"
                 "DONE_%=:\n\t}"
                 :: "r"(mbar), "r"(parity) : "memory");
}

// ---------------- conv: halo-reuse A (cp.async) + bulk-copy B (TMA 1D) + HMMA ----------------
// CTA: 128 padded M-rows x 128 out channels. A stage: 256 rows (tile+64 halo each side) x 64ch = 32KB.
#define A_ST 32768
#define B_ST 16384
#define SM_BYTES (2 * A_ST + 2 * B_ST)   // 98304

template <int TAPS>
__global__ void __launch_bounds__(256, 2) conv_kernel() {
    extern __shared__ __align__(128) char dsm[];
    __shared__ float s_scale[128];
    __shared__ float s_ps[32][2];
    __shared__ char s_mask[128];
    __shared__ __align__(8) unsigned long long s_mbar[2];

    const int tid = threadIdx.x, lane = tid & 31, warp = tid >> 5;
    const int wm = warp >> 2, wn = warp & 3;
    const int m0 = blockIdx.x * 128, o0 = blockIdx.y * 128;
    constexpr int NSTEP = TAPS * 4;

    const __nv_bfloat16* __restrict__ Bw = (TAPS == 9) ? g_Bp3 : g_Bp1;
    const float* __restrict__ scl = (TAPS == 9) ? g_scale3 : g_scale1;
    if (tid < 128) s_scale[tid] = scl[o0 + tid];

    const uint32_t sb = (uint32_t)__cvta_generic_to_shared(dsm);
    uint32_t mb[2] = { (uint32_t)__cvta_generic_to_shared(&s_mbar[0]),
                       (uint32_t)__cvta_generic_to_shared(&s_mbar[1]) };
    if (tid == 0) {
        asm volatile("mbarrier.init.shared.b64 [%0], 1;" :: "r"(mb[0]) : "memory");
        asm volatile("mbarrier.init.shared.b64 [%0], 1;" :: "r"(mb[1]) : "memory");
    }
    __syncthreads();

    float acc[4][4][4];
#pragma unroll
    for (int a = 0; a < 4; a++)
#pragma unroll
        for (int b = 0; b < 4; b++)
#pragma unroll
            for (int c = 0; c < 4; c++) acc[a][b][c] = 0.f;

    // A loader: thread = one of 256 rows [m0-64, m0+192); g_Sp row index = m0 + tid (guard folds in)
    auto loadA = [&](int kc, int st) {
        const __nv_bfloat16* src = g_Sp + ((size_t)(m0 + tid)) * CC + kc * 64;
        uint32_t dst = sb + st * A_ST;
#pragma unroll
        for (int s = 0; s < 8; s++) cpasync16(dst + swz(tid, s), src + s * 8);
        asm volatile("cp.async.commit_group;" ::: "memory");
    };
    auto issueB = [&](int idx) {   // tid==0 only
        int kc = idx / TAPS, t = idx - kc * TAPS;
        int blk = (TAPS == 9) ? (t * 4 + kc) : kc;
        const __nv_bfloat16* src = Bw + ((size_t)(blk * 256 + o0)) * 64;
        int s = idx & 1;
        asm volatile("mbarrier.arrive.expect_tx.shared.b64 _, [%0], %1;"
                     :: "r"(mb[s]), "r"((uint32_t)B_ST) : "memory");
        asm volatile("cp.async.bulk.shared::cluster.global.mbarrier::complete_tx::bytes [%0], [%1], %2, [%3];"
                     :: "r"(sb + 2 * A_ST + s * B_ST), "l"(src), "r"((uint32_t)B_ST), "r"(mb[s]) : "memory");
    };

    loadA(0, 0);
    if (tid == 0) issueB(0);
    uint32_t ph[2] = {0u, 0u};

#pragma unroll 1
    for (int kc = 0; kc < 4; kc++) {
        if (kc + 1 < 4) loadA(kc + 1, (kc + 1) & 1);
        if (kc < 3) asm volatile("cp.async.wait_group 1;" ::: "memory");
        else        asm volatile("cp.async.wait_group 0;" ::: "memory");
        __syncthreads();
        uint32_t stA = sb + (kc & 1) * A_ST;
#pragma unroll 1
        for (int t = 0; t < TAPS; t++) {
            int idx = kc * TAPS + t;
            int s = idx & 1;
            if (tid == 0 && idx + 1 < NSTEP) issueB(idx + 1);
            mbar_wait(mb[s], ph[s]); ph[s] ^= 1u;
            uint32_t stB = sb + 2 * A_ST + s * B_ST;
            int toff = (TAPS == 9) ? ((t / 3 - 1) * WPAD + (t % 3 - 1)) : 0;
#pragma unroll
            for (int ks = 0; ks < 4; ks++) {
                uint32_t a[4][4];
#pragma unroll
                for (int mf = 0; mf < 4; mf++) {
                    int row = 64 + toff + wm * 64 + mf * 16 + (lane & 15);
                    int seg = 2 * ks + (lane >> 4);
                    ldsm_x4(a[mf], stA + swz(row, seg));
                }
                uint32_t bq[2][4];
#pragma unroll
                for (int g = 0; g < 2; g++) {
                    int row = wn * 32 + g * 16 + (lane & 7) + (((lane >> 4) & 1) << 3);
                    int seg = 2 * ks + ((lane >> 3) & 1);
                    ldsm_x4(bq[g], stB + swz(row, seg));
                }
#pragma unroll
                for (int mf = 0; mf < 4; mf++)
#pragma unroll
                    for (int nf = 0; nf < 4; nf++)
                        mma16816(acc[mf][nf], a[mf], &bq[nf >> 1][(nf & 1) * 2]);
            }
            __syncthreads();
        }
    }

    // interior mask (exclude padded rows from BN sums)
    if (tid < 128) {
        int m = m0 + tid;
        int r = m % HWP;
        int hp = r / WPAD, wp = r - hp * WPAD;
        s_mask[tid] = (hp >= 1 && hp < 57 && wp >= 1 && wp < 57) ? 1 : 0;
    }
    __syncthreads();

    // epilogue: regs -> smem transpose (scaled) -> coalesced NHWC stores + masked BN sums
    float* Cs = (float*)dsm;
#pragma unroll 1
    for (int j = 0; j < 4; j++) {
        if (tid < 64) s_ps[tid >> 1][tid & 1] = 0.f;
        if (wn == j) {
#pragma unroll
            for (int mf = 0; mf < 4; mf++)
#pragma unroll
                for (int nf = 0; nf < 4; nf++) {
                    int row = wm * 64 + mf * 16 + (lane >> 2);
                    int col = nf * 8 + (lane & 3) * 2;
                    Cs[row * 33 + col]           = acc[mf][nf][0];
                    Cs[row * 33 + col + 1]       = acc[mf][nf][1];
                    Cs[(row + 8) * 33 + col]     = acc[mf][nf][2];
                    Cs[(row + 8) * 33 + col + 1] = acc[mf][nf][3];
                }
        }
        __syncthreads();
        {
            int c = tid & 31;
            float sc = s_scale[j * 32 + c];
            float s1 = 0.f, s2 = 0.f;
            int o = o0 + j * 32 + c;
#pragma unroll
            for (int i = 0; i < 16; i++) {
                int e = tid + 256 * i;
                int row = e >> 5;
                float v = Cs[row * 33 + c] * sc;
                g_conv[(size_t)(m0 + row) * CC + o] = v;
                float mk = (float)s_mask[row];
                s1 += v * mk; s2 += v * v * mk;
            }
            atomicAdd(&s_ps[c][0], s1);
            atomicAdd(&s_ps[c][1], s2);
        }
        __syncthreads();
        if (tid < 64) {
            atomicAdd(&g_part[(o0 + j * 32 + (tid >> 1)) * 2 + (tid & 1)], s_ps[tid >> 1][tid & 1]);
        }
        __syncthreads();
    }
}

// ---------------- BN stats: fold, then zero accumulators for graph-replay determinism ----------------
__global__ void stats_kernel(const float* __restrict__ gamma, const float* __restrict__ beta) {
    int c = threadIdx.x;
    float s1 = g_part[c * 2];
    float s2 = g_part[c * 2 + 1];
    float mean = s1 / (float)MTOT;
    float var  = s2 / (float)MTOT - mean * mean;
    float inv  = rsqrtf(var + 1e-5f);
    g_bnA[c] = gamma[c] * inv;
    g_bnB[c] = beta[c] - mean * gamma[c] * inv;
    g_part[c * 2] = 0.f;
    g_part[c * 2 + 1] = 0.f;
}

// ---------------- stage-1 tail: BN + residual + bias + PReLU + bias; emit x_mid & sign ----------------
__global__ void fuse1_kernel(const float* __restrict__ x, const float* __restrict__ b12,
                             const float* __restrict__ a1, const float* __restrict__ b13,
                             const float* __restrict__ b21) {
    __shared__ float xs[64][65];
    int hw0 = blockIdx.x * 64, c0 = blockIdx.y * 64, n = blockIdx.z;
    int tid = threadIdx.x;
#pragma unroll
    for (int i = 0; i < 16; i++) {
        int e = tid + 256 * i;
        int ci = e >> 6, hwi = e & 63;
        xs[ci][hwi] = x[((size_t)(n * CC + c0 + ci)) * HW + hw0 + hwi];
    }
    __syncthreads();
    int ci = tid & 63, c = c0 + ci;
    float A = g_bnA[c], B = g_bnB[c];
    float vb12 = b12[c], va = a1[c], vb13 = b13[c], vb21 = b21[c];
#pragma unroll
    for (int i = 0; i < 16; i++) {
        int e = tid + 256 * i;
        int hwi = e >> 6;
        int hw = hw0 + hwi;
        int h = hw / HHW, w = hw - h * HHW;
        size_t prow = (size_t)n * HWP + (h + 1) * WPAD + (w + 1);
        float y = xs[ci][hwi] + g_conv[prow * CC + c] * A + B;
        y += vb12;
        y = (y >= 0.f) ? y : va * y;
        y += vb13;
        g_xmid[prow * CC + c] = y;
        g_Sp[(GURD + prow) * CC + c] = __float2bfloat16(sgnf(y + vb21));
    }
}

// ---------------- stage-2 tail: BN + residual + bias + PReLU + bias; padded NHWC -> NCHW out ----------------
__global__ void fuse2_kernel(const float* __restrict__ b22, const float* __restrict__ a2,
                             const float* __restrict__ b23, float* __restrict__ out) {
    __shared__ float ys[64][65];
    int hw0 = blockIdx.x * 64, c0 = blockIdx.y * 64, n = blockIdx.z;
    int tid = threadIdx.x;
    int ci = tid & 63, c = c0 + ci;
    float A = g_bnA[c], B = g_bnB[c];
    float vb22 = b22[c], va = a2[c], vb23 = b23[c];
#pragma unroll
    for (int i = 0; i < 16; i++) {
        int e = tid + 256 * i;
        int hwi = e >> 6;
        int hw = hw0 + hwi;
        int h = hw / HHW, w = hw - h * HHW;
        size_t prow = (size_t)n * HWP + (h + 1) * WPAD + (w + 1);
        float y = g_conv[prow * CC + c] * A + B + g_xmid[prow * CC + c];
        y += vb22;
        y = (y >= 0.f) ? y : va * y;
        y += vb23;
        ys[ci][hwi] = y;
    }
    __syncthreads();
#pragma unroll
    for (int i = 0; i < 16; i++) {
        int e = tid + 256 * i;
        int c2 = e >> 6, hwi = e & 63;
        out[((size_t)(n * CC + c0 + c2)) * HW + hw0 + hwi] = ys[c2][hwi];
    }
}

// ---------------- launch ----------------
extern "C" void kernel_launch(void* const* d_in, const int* in_sizes, int n_in,
                              void* d_out, int out_size) {
    (void)in_sizes; (void)n_in; (void)out_size;
    const float* x     = (const float*)d_in[0];
    const float* b1_1  = (const float*)d_in[1];
    const float* w3x3  = (const float*)d_in[2];
    const float* bn1_g = (const float*)d_in[3];
    const float* bn1_b = (const float*)d_in[4];
    const float* b1_2  = (const float*)d_in[5];
    const float* a1    = (const float*)d_in[6];
    const float* b1_3  = (const float*)d_in[7];
    const float* b2_1  = (const float*)d_in[8];
    const float* wres  = (const float*)d_in[9];
    const float* bn2_g = (const float*)d_in[10];
    const float* bn2_b = (const float*)d_in[11];
    const float* b2_2  = (const float*)d_in[12];
    const float* a2    = (const float*)d_in[13];
    const float* b2_3  = (const float*)d_in[14];
    float* out = (float*)d_out;

    cudaFuncSetAttribute(conv_kernel<9>, cudaFuncAttributeMaxDynamicSharedMemorySize, SM_BYTES);
    cudaFuncSetAttribute(conv_kernel<1>, cudaFuncAttributeMaxDynamicSharedMemorySize, SM_BYTES);

    dim3 tileGrid(49, 4, 32);
    dim3 convGrid(841, 2);

    wprep3_kernel<<<256, 256>>>(w3x3);
    wprep1_kernel<<<256, 256>>>(wres);
    sign_in_kernel<<<tileGrid, 256>>>(x, b1_1);
    conv_kernel<9><<<convGrid, 256, SM_BYTES>>>();
    stats_kernel<<<1, 256>>>(bn1_g, bn1_b);
    fuse1_kernel<<<tileGrid, 256>>>(x, b1_2, a1, b1_3, b2_1);
    conv_kernel<1><<<convGrid, 256, SM_BYTES>>>();
    stats_kernel<<<1, 256>>>(bn2_g, bn2_b);
    fuse2_kernel<<<tileGrid, 256>>>(b2_2, a2, b2_3, out);
}